// round 8
// baseline (speedup 1.0000x reference)
#include <cuda_runtime.h>
#include <math_constants.h>

#define W      8192
#define ROWS   4096      // 16 * 1 * 256
#define NLAG   4096      // W / 2
#define TPB    512
#define EPT    16        // elements per thread (TPB * EPT == W)
#define NWARP  (TPB / 32)
#define CAP    256       // candidate buffer capacity (expected ~3-8 used)

__device__ __forceinline__ bool better(float v, int i, float v2, int i2) {
    return (v > v2) || (v == v2 && i < i2);
}

__device__ __forceinline__ void ins3(float v, int i,
                                     float& s0, int& i0,
                                     float& s1, int& i1,
                                     float& s2, int& i2) {
    if (better(v, i, s0, i0)) {
        s2 = s1; i2 = i1;
        s1 = s0; i1 = i0;
        s0 = v;  i0 = i;
    } else if (better(v, i, s1, i1)) {
        s2 = s1; i2 = i1;
        s1 = v;  i1 = i;
    } else if (better(v, i, s2, i2)) {
        s2 = v;  i2 = i;
    }
}

// Merge sorted (desc) value triple (b0,b1,b2) into (a0,a1,a2). FMNMX net.
__device__ __forceinline__ void merge3(float& a0, float& a1, float& a2,
                                       float b0, float b1, float b2) {
    float r0 = fmaxf(a0, b0);
    float x  = fminf(a0, b0);
    float y  = fmaxf(a1, b1);
    float z  = fminf(a1, b1);
    float r1 = fmaxf(x, y);
    float s  = fminf(x, y);
    float r2 = fmaxf(fmaxf(s, z), fmaxf(a2, b2));
    a0 = r0; a1 = r1; a2 = r2;
}

__global__ __launch_bounds__(TPB, 4)
void peaks_kernel(const float* __restrict__ x, float* __restrict__ out) {
    const int row = blockIdx.x;
    const float* __restrict__ xr = x + (size_t)row * W;
    const int t   = threadIdx.x;
    const int lid = t & 31;
    const int wid = t >> 5;
    const int start = t * EPT;
    const unsigned fm = 0xffffffffu;

    __shared__ float s_wmax[NWARP];
    __shared__ float s_t;
    __shared__ int   s_cnt;
    __shared__ float s_val[CAP];
    __shared__ int   s_idx[CAP];

    if (t == 0) s_cnt = 0;   // ordered before phase-2 atomics by B2+B3

    // ---- Load chunk (4x LDG.128, front-batched) + halo scalar loads ----
    float c[EPT];
    const float4* p = reinterpret_cast<const float4*>(xr + start);
    float qm[EPT / 4];
#pragma unroll
    for (int q = 0; q < EPT / 4; q++) {
        float4 v = p[q];
        c[q * 4 + 0] = v.x;
        c[q * 4 + 1] = v.y;
        c[q * 4 + 2] = v.z;
        c[q * 4 + 3] = v.w;
        qm[q] = fmaxf(fmaxf(v.x, v.y), fmaxf(v.z, v.w));
    }
    float pl = -CUDART_INF_F, pn = -CUDART_INF_F;
    if (lid == 0  && t > 0)        pl = __ldg(xr + start - 1);
    if (lid == 31 && t < TPB - 1)  pn = __ldg(xr + start + EPT);

    // ---- Halo: intra-warp shuffle, no block barrier ----
    float vprev = __shfl_up_sync(fm, c[EPT - 1], 1);
    float vnext = __shfl_down_sync(fm, c[0], 1);
    if (lid == 0)  vprev = pl;
    if (lid == 31) vnext = pn;

    // ---- Phase 1: RAW chunk max only (1 op/element, pure FMNMX tree) ----
    const float myMax = fmaxf(fmaxf(qm[0], qm[1]), fmaxf(qm[2], qm[3]));

    // ---- Warp edge-peak scores (only boundary elements can be non-peaks
    //      when the warp raw max sits on them) ----
    float ep = 0.0f;
    if (lid == 0)  ep = (c[0]       >= fmaxf(vprev,      c[1]))   ? c[0]       : 0.0f;
    if (lid == 31) ep = (c[EPT - 1] >= fmaxf(c[EPT - 2], vnext))  ? c[EPT - 1] : 0.0f;

    // Broadcasts needed for the safety select (warp-collective).
    const float wfirst = __shfl_sync(fm, c[0],       0);
    const float wlast  = __shfl_sync(fm, c[EPT - 1], 31);
    const float efirst = __shfl_sync(fm, ep, 0);
    const float elast  = __shfl_sync(fm, ep, 31);

    // ---- Plain warp max of raw chunk maxima ----
    float wmax = myMax;
#pragma unroll
    for (int off = 16; off; off >>= 1)
        wmax = fmaxf(wmax, __shfl_down_sync(fm, wmax, off));

    if (lid == 0) {
        // If the warp raw max is strictly interior, it IS a peak (>= both
        // neighbors, which lie inside the span). Otherwise fall back to the
        // exact edge-peak scores (an underestimate -> looser thr -> safe).
        const float safe = (wmax > wfirst && wmax > wlast)
                               ? wmax : fmaxf(efirst, elast);
        s_wmax[wid] = safe;
    }
    __syncthreads();                                          // B2

    // ---- Warp 0 ONLY: 3rd-largest of 16 warp values -> block threshold ----
    if (wid == 0) {
        float u0 = (lid < NWARP) ? s_wmax[lid] : -CUDART_INF_F;
        float u1 = -CUDART_INF_F, u2 = -CUDART_INF_F;
#pragma unroll
        for (int off = 8; off; off >>= 1) {
            float b0 = __shfl_down_sync(fm, u0, off);
            float b1 = __shfl_down_sync(fm, u1, off);
            float b2 = __shfl_down_sync(fm, u2, off);
            merge3(u0, u1, u2, b0, b1, b2);
        }
        if (lid == 0) s_t = u2;
    }
    __syncthreads();                                          // B3

    // ---- Phase 2: gated threads recompute exact scores and push ----
    const float thr = s_t;
    if (myMax >= thr) {            // raw max >= any peak score -> safe gate
        float prev = vprev;
#pragma unroll
        for (int j = 0; j < EPT; j++) {
            const float v = c[j];
            const float r = (j == EPT - 1) ? vnext : c[j + 1];
            const float mx = fmaxf(prev, r);
            const float sc = (v >= mx) ? v : 0.0f;
            // sc > 0 guard: prevents degenerate flood if thr <= 0
            if (sc >= thr && sc > 0.0f) {
                int pos = atomicAdd(&s_cnt, 1);
                if (pos < CAP) { s_val[pos] = sc; s_idx[pos] = start + j; }
            }
            prev = v;
        }
    }
    __syncthreads();                                          // B4

    // ---- Thread 0: exact top-3 over tiny candidate list, then outputs ----
    if (t == 0) {
        int n = s_cnt; if (n > CAP) n = CAP;
        float s0 = -CUDART_INF_F, s1 = -CUDART_INF_F, s2 = -CUDART_INF_F;
        int   i0 = 0x7fffffff,    i1 = 0x7fffffff,    i2 = 0x7fffffff;
        for (int k = 0; k < n; k++)
            ins3(s_val[k], s_idx[k], s0, i0, s1, i1, s2, i2);

        // Output layout (return order, all fp32):
        //   [0       , ROWS*3) : neighbor_score
        //   [ROWS*3  , ROWS*6) : topk_scores
        //   [ROWS*6  , ROWS*9) : topk_index (int values, exact in fp32)
        const int top = i0;
#pragma unroll
        for (int k = 0; k < 3; k++) {
            int nb = top - 1 + k;
            nb = nb < 0 ? 0 : (nb > W - 1 ? W - 1 : nb);
            out[(size_t)row * 3 + k] = __ldg(xr + nb);
        }
        const float ts[3] = {s0, s1, s2};
        const int   ti[3] = {i0, i1, i2};
#pragma unroll
        for (int k = 0; k < 3; k++) {
            out[(size_t)ROWS * 3 + (size_t)row * 3 + k] = ts[k];
            out[(size_t)ROWS * 6 + (size_t)row * 3 + k] = (float)(ti[k] - NLAG);
        }
    }
}

extern "C" void kernel_launch(void* const* d_in, const int* in_sizes, int n_in,
                              void* d_out, int out_size) {
    const float* x = (const float*)d_in[0];
    float* out = (float*)d_out;
    (void)in_sizes; (void)n_in; (void)out_size;
    peaks_kernel<<<ROWS, TPB>>>(x, out);
}